// round 12
// baseline (speedup 1.0000x reference)
#include <cuda_runtime.h>
#include <cuda_fp16.h>
#include <cstdint>

#define BT_TOTAL 4096
#define T_SEQ    2048
#define EMB      2048
#define FD       3072
#define NH       32
#define NG       8
#define HD       64
#define GBK      64
#define NCH      (EMB / GBK)    // 32

// ---------------- device scratch (no allocations allowed) ----------------
__device__ __half g_qh[(size_t)2 * NH * T_SEQ * HD];
__device__ __half g_ql[(size_t)2 * NH * T_SEQ * HD];
__device__ __half g_kh[(size_t)2 * NG * T_SEQ * HD];
__device__ __half g_vh[(size_t)2 * NG * T_SEQ * HD];

__device__ __half g_xh[(size_t)BT_TOTAL * EMB];
__device__ __half g_w1h[(size_t)FD * EMB];
__device__ __half g_w2h[(size_t)EMB * EMB];
__device__ __half g_atth[(size_t)BT_TOTAL * EMB];

// ---------------- helpers ----------------
__device__ __forceinline__ uint32_t smem_u32(const void* p) {
    uint32_t a;
    asm("{ .reg .u64 t; cvta.to.shared.u64 t, %1; cvt.u32.u64 %0, t; }" : "=r"(a) : "l"(p));
    return a;
}
__device__ __forceinline__ void cp16(uint32_t dst, const void* src) {
    asm volatile("cp.async.cg.shared.global [%0], [%1], 16;" :: "r"(dst), "l"(src));
}
__device__ __forceinline__ void ldsm_x4(uint32_t addr, uint32_t* r) {
    asm volatile("ldmatrix.sync.aligned.m8n8.x4.shared.b16 {%0,%1,%2,%3}, [%4];"
        : "=r"(r[0]), "=r"(r[1]), "=r"(r[2]), "=r"(r[3]) : "r"(addr));
}
__device__ __forceinline__ void ldsm_x2(uint32_t addr, uint32_t* r) {
    asm volatile("ldmatrix.sync.aligned.m8n8.x2.shared.b16 {%0,%1}, [%2];"
        : "=r"(r[0]), "=r"(r[1]) : "r"(addr));
}
__device__ __forceinline__ void ldsm_x2t(uint32_t addr, uint32_t* r) {
    asm volatile("ldmatrix.sync.aligned.m8n8.x2.trans.shared.b16 {%0,%1}, [%2];"
        : "=r"(r[0]), "=r"(r[1]) : "r"(addr));
}
__device__ __forceinline__ void mma_f16(float* c, const uint32_t* a, const uint32_t* b) {
    asm volatile("mma.sync.aligned.m16n8k16.row.col.f32.f16.f16.f32 "
        "{%0,%1,%2,%3}, {%4,%5,%6,%7}, {%8,%9}, {%0,%1,%2,%3};"
        : "+f"(c[0]), "+f"(c[1]), "+f"(c[2]), "+f"(c[3])
        : "r"(a[0]), "r"(a[1]), "r"(a[2]), "r"(a[3]), "r"(b[0]), "r"(b[1]));
}

// ---------------- convert fp32 -> fp16 ----------------
__global__ void to_half(const float* __restrict__ src, __half* __restrict__ dst, int n4) {
    int i = blockIdx.x * blockDim.x + threadIdx.x;
    if (i >= n4) return;
    float4 v = *(const float4*)(src + (size_t)i * 4);
    __half2 a = __floats2half2_rn(v.x, v.y);
    __half2 b = __floats2half2_rn(v.z, v.w);
    ((__half2*)dst)[i * 2]     = a;
    ((__half2*)dst)[i * 2 + 1] = b;
}

// ---------------- fp16 HMMA GEMM: 512 threads, tile 256x128, warp 32x64 ----------------
// ROPE_EPI=0: C[M,N] fp32 plain store.  ROPE_EPI=1: fused rope+scatter to q/k/v fp16.
#define GSTG 49152                      // A 32KB + B 16KB per stage
#define GEMM_SMEM (3 * GSTG)
template <int ROPE_EPI>
__global__ __launch_bounds__(512, 1) void gemm_hmma(
    const __half* __restrict__ A, const __half* __restrict__ B,
    float* __restrict__ C, int N,
    const float* __restrict__ cosb, const float* __restrict__ sinb) {
    extern __shared__ __align__(1024) char smem[];
    const uint32_t sbase = smem_u32(smem);
    const int tid = threadIdx.x;
    const int wid = tid >> 5, lane = tid & 31;
    const int bm = blockIdx.y * 256, bn = blockIdx.x * 128;
    const int warp_m = wid & 7, warp_n = wid >> 3;   // 8 x 2, warp tile 32x64

    auto load_chunk = [&](int chunk, int stage) {
        const uint32_t sA = sbase + stage * GSTG;
        const uint32_t sB = sA + 32768;
#pragma unroll
        for (int i = 0; i < 4; i++) {                 // A: 256 rows x 8 c16
            int id = i * 512 + tid;
            int row = id >> 3, c16 = id & 7;
            uint32_t off = (uint32_t)(row * 128 + ((c16 ^ (row & 7)) << 4));
            cp16(sA + off, A + (size_t)(bm + row) * EMB + chunk * GBK + c16 * 8);
        }
#pragma unroll
        for (int i = 0; i < 2; i++) {                 // B: 128 rows x 8 c16
            int id = i * 512 + tid;
            int row = id >> 3, c16 = id & 7;
            uint32_t off = (uint32_t)(row * 128 + ((c16 ^ (row & 7)) << 4));
            cp16(sB + off, B + (size_t)(bn + row) * EMB + chunk * GBK + c16 * 8);
        }
        asm volatile("cp.async.commit_group;" ::: "memory");
    };

    float acc[2][8][4];
#pragma unroll
    for (int mf = 0; mf < 2; mf++)
#pragma unroll
        for (int nf = 0; nf < 8; nf++)
#pragma unroll
            for (int q = 0; q < 4; q++) acc[mf][nf][q] = 0.f;

    load_chunk(0, 0);
    load_chunk(1, 1);

    for (int c = 0; c < NCH; c++) {
        asm volatile("cp.async.wait_group 1;" ::: "memory");
        __syncthreads();
        if (c + 2 < NCH) load_chunk(c + 2, (c + 2) % 3);
        else asm volatile("cp.async.commit_group;" ::: "memory");

        const uint32_t sA = sbase + (c % 3) * GSTG;
        const uint32_t sB = sA + 32768;
#pragma unroll
        for (int kf = 0; kf < 4; kf++) {
            uint32_t afr[2][4];
#pragma unroll
            for (int mf = 0; mf < 2; mf++) {
                int row = warp_m * 32 + mf * 16 + (lane & 15);
                int c16 = kf * 2 + (lane >> 4);
                ldsm_x4(sA + row * 128 + ((c16 ^ (row & 7)) << 4), afr[mf]);
            }
            uint32_t bfr[4][4];
#pragma unroll
            for (int nf2 = 0; nf2 < 4; nf2++) {
                int nrow = warp_n * 64 + nf2 * 16 + ((lane >> 4) << 3) + (lane & 7);
                int c16 = kf * 2 + ((lane >> 3) & 1);
                ldsm_x4(sB + nrow * 128 + ((c16 ^ (nrow & 7)) << 4), bfr[nf2]);
            }
#pragma unroll
            for (int mf = 0; mf < 2; mf++)
#pragma unroll
                for (int nf2 = 0; nf2 < 4; nf2++) {
                    mma_f16(acc[mf][2 * nf2],     afr[mf], &bfr[nf2][0]);
                    mma_f16(acc[mf][2 * nf2 + 1], afr[mf], &bfr[nf2][2]);
                }
        }
    }

    if (ROPE_EPI == 0) {
#pragma unroll
        for (int mf = 0; mf < 2; mf++) {
            int row = bm + warp_m * 32 + mf * 16 + (lane >> 2);
#pragma unroll
            for (int nf = 0; nf < 8; nf++) {
                int col = bn + warp_n * 64 + nf * 8 + (lane & 3) * 2;
                *(float2*)(C + (size_t)row * N + col)       = make_float2(acc[mf][nf][0], acc[mf][nf][1]);
                *(float2*)(C + (size_t)(row + 8) * N + col) = make_float2(acc[mf][nf][2], acc[mf][nf][3]);
            }
        }
    } else {
        // fused rope + scatter. Warp's 64-col tile = one head slot.
        int hidx = (bn >> 6) + warp_n;          // g*6 + slot
        int g = hidx / 6, slot = hidx % 6;
#pragma unroll
        for (int mf = 0; mf < 2; mf++) {
#pragma unroll
            for (int rr = 0; rr < 2; rr++) {
                int row = bm + warp_m * 32 + mf * 16 + (lane >> 2) + rr * 8;
                int b = row >> 11, t = row & (T_SEQ - 1);
#pragma unroll
                for (int nf = 0; nf < 4; nf++) {
                    int d = nf * 8 + (lane & 3) * 2;
                    float x1a = acc[mf][nf][2 * rr],     x1b = acc[mf][nf][2 * rr + 1];
                    float x2a = acc[mf][nf + 4][2 * rr], x2b = acc[mf][nf + 4][2 * rr + 1];
                    if (slot == 5) {
                        __half* dst = g_vh + ((size_t)(b * NG + g) * T_SEQ + t) * HD;
                        *(__half2*)(dst + d)      = __floats2half2_rn(x1a, x1b);
                        *(__half2*)(dst + d + 32) = __floats2half2_rn(x2a, x2b);
                    } else {
                        float2 cc = *(const float2*)(cosb + t * 32 + d);
                        float2 ss = *(const float2*)(sinb + t * 32 + d);
                        float y1a = x1a * cc.x - x2a * ss.x;
                        float y1b = x1b * cc.y - x2b * ss.y;
                        float y2a = x2a * cc.x + x1a * ss.x;
                        float y2b = x2b * cc.y + x1b * ss.y;
                        if (slot == 4) {
                            __half* dst = g_kh + ((size_t)(b * NG + g) * T_SEQ + t) * HD;
                            *(__half2*)(dst + d)      = __floats2half2_rn(y1a, y1b);
                            *(__half2*)(dst + d + 32) = __floats2half2_rn(y2a, y2b);
                        } else {
                            size_t o = ((size_t)(b * NH + g * 4 + slot) * T_SEQ + t) * HD;
                            __half2 h1 = __floats2half2_rn(y1a, y1b);
                            __half2 h2 = __floats2half2_rn(y2a, y2b);
                            *(__half2*)(g_qh + o + d)      = h1;
                            *(__half2*)(g_qh + o + d + 32) = h2;
                            float2 f1 = __half22float2(h1), f2 = __half22float2(h2);
                            *(__half2*)(g_ql + o + d)      = __floats2half2_rn(y1a - f1.x, y1b - f1.y);
                            *(__half2*)(g_ql + o + d + 32) = __floats2half2_rn(y2a - f2.x, y2b - f2.y);
                        }
                    }
                }
            }
        }
    }
}

// ---------------- HMMA flash attention (fp16, q hi/lo split, non-causal) ----------------
#define ABR 128
#define ABC 64
#define ATT_SMEM (32768 + 2 * 16384)
__global__ __launch_bounds__(256, 1) void attn_hmma() {
    extern __shared__ __align__(1024) char smem[];
    const uint32_t sb = smem_u32(smem);
    const uint32_t Qs = sb;            // [128 rows][256B]  (hi c16 0-7 | lo c16 8-15)
    const uint32_t KVs = sb + 32768;   // 2 stages x (K 8192 + V 8192)

    const int tid = threadIdx.x;
    const int w = tid >> 5, lane = tid & 31;
    const int qt = blockIdx.x, bh = blockIdx.y;
    const int b = bh >> 5, h = bh & 31, g = h >> 2;
    const int q0 = qt * ABR;

    const __half* qhb = g_qh + ((size_t)(b * NH + h) * T_SEQ + q0) * HD;
    const __half* qlb = g_ql + ((size_t)(b * NH + h) * T_SEQ + q0) * HD;
    const __half* khb = g_kh + (size_t)(b * NG + g) * T_SEQ * HD;
    const __half* vhb = g_vh + (size_t)(b * NG + g) * T_SEQ * HD;

#pragma unroll
    for (int i = 0; i < 8; i++) {
        int id = i * 256 + tid;
        int row = id >> 4, c16 = id & 15;
        uint32_t off = (uint32_t)(row * 256 + ((((c16 ^ row) & 7) | (c16 & 8)) << 4));
        const __half* src = (c16 < 8) ? (qhb + row * 64 + c16 * 8)
                                      : (qlb + row * 64 + (c16 - 8) * 8);
        cp16(Qs + off, src);
    }
    asm volatile("cp.async.commit_group;" ::: "memory");

    auto loadKV = [&](int t, int s) {
        uint32_t base = KVs + s * 16384;
#pragma unroll
        for (int i = 0; i < 2; i++) {
            int id = i * 256 + tid;
            int row = id >> 3, c8 = id & 7;
            uint32_t off = (uint32_t)(row * 128 + ((c8 ^ (row & 7)) << 4));
            size_t ga = (size_t)(t * ABC + row) * 64 + c8 * 8;
            cp16(base + off, khb + ga);
            cp16(base + 8192 + off, vhb + ga);
        }
        asm volatile("cp.async.commit_group;" ::: "memory");
    };
    loadKV(0, 0);

    float oacc[8][4];
#pragma unroll
    for (int nf = 0; nf < 8; nf++)
#pragma unroll
        for (int q = 0; q < 4; q++) oacc[nf][q] = 0.f;
    float m0 = -1e30f, m1 = -1e30f, l0 = 0.f, l1 = 0.f;
    const float sc = 0.125f;

    const int NT = T_SEQ / ABC;
    for (int t = 0; t < NT; t++) {
        if (t + 1 < NT) { loadKV(t + 1, (t + 1) & 1); asm volatile("cp.async.wait_group 1;" ::: "memory"); }
        else            { asm volatile("cp.async.wait_group 0;" ::: "memory"); }
        __syncthreads();
        const uint32_t kb = KVs + (t & 1) * 16384;
        const uint32_t vb = kb + 8192;

        float sacc[8][4];
#pragma unroll
        for (int nf = 0; nf < 8; nf++)
#pragma unroll
            for (int q = 0; q < 4; q++) sacc[nf][q] = 0.f;

#pragma unroll
        for (int kf = 0; kf < 4; kf++) {
            uint32_t ah[4], al[4];
            {
                int row = w * 16 + (lane & 15);
                int c16h = kf * 2 + (lane >> 4);
                int c16l = 8 + kf * 2 + (lane >> 4);
                ldsm_x4(Qs + row * 256 + ((((c16h ^ row) & 7) | (c16h & 8)) << 4), ah);
                ldsm_x4(Qs + row * 256 + ((((c16l ^ row) & 7) | (c16l & 8)) << 4), al);
            }
#pragma unroll
            for (int nf = 0; nf < 8; nf++) {
                uint32_t bk[2];
                int nrow = nf * 8 + (lane & 7);
                int c8 = kf * 2 + ((lane >> 3) & 1);
                ldsm_x2(kb + nrow * 128 + ((c8 ^ (nrow & 7)) << 4), bk);
                mma_f16(sacc[nf], ah, bk);
                mma_f16(sacc[nf], al, bk);
            }
        }

        float mx0 = -1e30f, mx1 = -1e30f;
#pragma unroll
        for (int nf = 0; nf < 8; nf++) {
            mx0 = fmaxf(mx0, fmaxf(sacc[nf][0], sacc[nf][1]));
            mx1 = fmaxf(mx1, fmaxf(sacc[nf][2], sacc[nf][3]));
        }
        mx0 = fmaxf(mx0, __shfl_xor_sync(0xffffffff, mx0, 1));
        mx0 = fmaxf(mx0, __shfl_xor_sync(0xffffffff, mx0, 2));
        mx1 = fmaxf(mx1, __shfl_xor_sync(0xffffffff, mx1, 1));
        mx1 = fmaxf(mx1, __shfl_xor_sync(0xffffffff, mx1, 2));
        float mn0 = fmaxf(m0, mx0 * sc);
        float mn1 = fmaxf(m1, mx1 * sc);
        float a0 = __expf(m0 - mn0), a1 = __expf(m1 - mn1);
        m0 = mn0; m1 = mn1;

        uint32_t pa[16];
        float s0 = 0.f, s1 = 0.f;
#pragma unroll
        for (int nf = 0; nf < 8; nf++) {
            float p0 = __expf(sacc[nf][0] * sc - mn0);
            float p1 = __expf(sacc[nf][1] * sc - mn0);
            float p2 = __expf(sacc[nf][2] * sc - mn1);
            float p3 = __expf(sacc[nf][3] * sc - mn1);
            s0 += p0 + p1; s1 += p2 + p3;
            __half2 h01 = __floats2half2_rn(p0, p1);
            __half2 h23 = __floats2half2_rn(p2, p3);
            pa[2 * nf]     = *(uint32_t*)&h01;
            pa[2 * nf + 1] = *(uint32_t*)&h23;
        }
        l0 = l0 * a0 + s0;
        l1 = l1 * a1 + s1;
#pragma unroll
        for (int nf = 0; nf < 8; nf++) {
            oacc[nf][0] *= a0; oacc[nf][1] *= a0;
            oacc[nf][2] *= a1; oacc[nf][3] *= a1;
        }

#pragma unroll
        for (int kf2 = 0; kf2 < 4; kf2++) {
            uint32_t a[4] = { pa[4 * kf2], pa[4 * kf2 + 1], pa[4 * kf2 + 2], pa[4 * kf2 + 3] };
#pragma unroll
            for (int nf = 0; nf < 8; nf++) {
                uint32_t bv[2];
                int vrow = kf2 * 16 + (lane & 15);
                int c8 = nf;
                ldsm_x2t(vb + vrow * 128 + ((c8 ^ (vrow & 7)) << 4), bv);
                mma_f16(oacc[nf], a, bv);
            }
        }
        __syncthreads();
    }

    l0 += __shfl_xor_sync(0xffffffff, l0, 1);
    l0 += __shfl_xor_sync(0xffffffff, l0, 2);
    l1 += __shfl_xor_sync(0xffffffff, l1, 1);
    l1 += __shfl_xor_sync(0xffffffff, l1, 2);
    float inv0 = 1.f / l0, inv1 = 1.f / l1;

    int r0 = lane >> 2;
    size_t row0 = (size_t)(b * T_SEQ + q0 + w * 16 + r0) * EMB;
    size_t row1 = row0 + 8 * EMB;
#pragma unroll
    for (int nf = 0; nf < 8; nf++) {
        int col = h * 64 + nf * 8 + (lane & 3) * 2;
        __half2 o01 = __floats2half2_rn(oacc[nf][0] * inv0, oacc[nf][1] * inv0);
        __half2 o23 = __floats2half2_rn(oacc[nf][2] * inv1, oacc[nf][3] * inv1);
        *(__half2*)(g_atth + row0 + col) = o01;
        *(__half2*)(g_atth + row1 + col) = o23;
    }
}

// ---------------- launch ----------------
extern "C" void kernel_launch(void* const* d_in, const int* in_sizes, int n_in,
                              void* d_out, int out_size) {
    const float* x      = (const float*)d_in[0];
    const float* cosb   = (const float*)d_in[1];
    const float* sinb   = (const float*)d_in[2];
    const float* attn_w = (const float*)d_in[3];
    const float* proj_w = (const float*)d_in[4];
    float* out = (float*)d_out;

    __half *xh, *w1h, *w2h, *atth;
    cudaGetSymbolAddress((void**)&xh, g_xh);
    cudaGetSymbolAddress((void**)&w1h, g_w1h);
    cudaGetSymbolAddress((void**)&w2h, g_w2h);
    cudaGetSymbolAddress((void**)&atth, g_atth);

    cudaFuncSetAttribute(gemm_hmma<0>, cudaFuncAttributeMaxDynamicSharedMemorySize, GEMM_SMEM);
    cudaFuncSetAttribute(gemm_hmma<1>, cudaFuncAttributeMaxDynamicSharedMemorySize, GEMM_SMEM);
    cudaFuncSetAttribute(attn_hmma, cudaFuncAttributeMaxDynamicSharedMemorySize, ATT_SMEM);

    // convert inputs to fp16
    {
        int n4 = BT_TOTAL * EMB / 4;
        to_half<<<(n4 + 255) / 256, 256>>>(x, xh, n4);
        n4 = FD * EMB / 4;
        to_half<<<(n4 + 255) / 256, 256>>>(attn_w, w1h, n4);
        n4 = EMB * EMB / 4;
        to_half<<<(n4 + 255) / 256, 256>>>(proj_w, w2h, n4);
    }

    // 1) qkv = x @ attn_w^T with fused rope + scatter to fp16 q(hi/lo)/k/v
    gemm_hmma<1><<<dim3(FD / 128, BT_TOTAL / 256), 512, GEMM_SMEM>>>(
        xh, w1h, nullptr, FD, cosb, sinb);

    // 2) HMMA flash attention -> g_atth (fp16)
    attn_hmma<<<dim3(T_SEQ / ABR, 2 * NH), 256, ATT_SMEM>>>();

    // 3) out = att @ proj_w^T (fp32 out)
    gemm_hmma<0><<<dim3(EMB / 128, BT_TOTAL / 256), 512, GEMM_SMEM>>>(
        atth, w2h, out, EMB, nullptr, nullptr);
}

// round 13
// speedup vs baseline: 1.5184x; 1.5184x over previous
#include <cuda_runtime.h>
#include <cuda_fp16.h>
#include <cstdint>

#define BT_TOTAL 4096
#define T_SEQ    2048
#define EMB      2048
#define FD       3072
#define NH       32
#define NG       8
#define HD       64
#define GBK      64
#define NCH      (EMB / GBK)    // 32

// ---------------- device scratch (no allocations allowed) ----------------
__device__ __half g_qh[(size_t)2 * NH * T_SEQ * HD];
__device__ __half g_ql[(size_t)2 * NH * T_SEQ * HD];
__device__ __half g_kh[(size_t)2 * NG * T_SEQ * HD];
__device__ __half g_vh[(size_t)2 * NG * T_SEQ * HD];

__device__ __half g_xh[(size_t)BT_TOTAL * EMB];
__device__ __half g_w1h[(size_t)FD * EMB];
__device__ __half g_w2h[(size_t)EMB * EMB];
__device__ __half g_atth[(size_t)BT_TOTAL * EMB];

// ---------------- helpers ----------------
__device__ __forceinline__ uint32_t smem_u32(const void* p) {
    uint32_t a;
    asm("{ .reg .u64 t; cvta.to.shared.u64 t, %1; cvt.u32.u64 %0, t; }" : "=r"(a) : "l"(p));
    return a;
}
__device__ __forceinline__ void cp16(uint32_t dst, const void* src) {
    asm volatile("cp.async.cg.shared.global [%0], [%1], 16;" :: "r"(dst), "l"(src));
}
__device__ __forceinline__ void ldsm_x4(uint32_t addr, uint32_t* r) {
    asm volatile("ldmatrix.sync.aligned.m8n8.x4.shared.b16 {%0,%1,%2,%3}, [%4];"
        : "=r"(r[0]), "=r"(r[1]), "=r"(r[2]), "=r"(r[3]) : "r"(addr));
}
__device__ __forceinline__ void ldsm_x2(uint32_t addr, uint32_t* r) {
    asm volatile("ldmatrix.sync.aligned.m8n8.x2.shared.b16 {%0,%1}, [%2];"
        : "=r"(r[0]), "=r"(r[1]) : "r"(addr));
}
__device__ __forceinline__ void ldsm_x2t(uint32_t addr, uint32_t* r) {
    asm volatile("ldmatrix.sync.aligned.m8n8.x2.trans.shared.b16 {%0,%1}, [%2];"
        : "=r"(r[0]), "=r"(r[1]) : "r"(addr));
}
__device__ __forceinline__ void mma_f16(float* c, const uint32_t* a, const uint32_t* b) {
    asm volatile("mma.sync.aligned.m16n8k16.row.col.f32.f16.f16.f32 "
        "{%0,%1,%2,%3}, {%4,%5,%6,%7}, {%8,%9}, {%0,%1,%2,%3};"
        : "+f"(c[0]), "+f"(c[1]), "+f"(c[2]), "+f"(c[3])
        : "r"(a[0]), "r"(a[1]), "r"(a[2]), "r"(a[3]), "r"(b[0]), "r"(b[1]));
}

// ---------------- convert fp32 -> fp16 ----------------
__global__ void to_half(const float* __restrict__ src, __half* __restrict__ dst, int n4) {
    int i = blockIdx.x * blockDim.x + threadIdx.x;
    if (i >= n4) return;
    float4 v = *(const float4*)(src + (size_t)i * 4);
    __half2 a = __floats2half2_rn(v.x, v.y);
    __half2 b = __floats2half2_rn(v.z, v.w);
    ((__half2*)dst)[i * 2]     = a;
    ((__half2*)dst)[i * 2 + 1] = b;
}

// ---------------- fp16 HMMA GEMM: 256 threads, tile 256x128, warp 64x64 (4x2) --------
// ROPE_EPI=0: C[M,N] fp32 plain store.  ROPE_EPI=1: fused rope+scatter to q/k/v fp16.
#define GSTG 49152                      // A 32KB + B 16KB per stage
#define GEMM_SMEM (3 * GSTG)
template <int ROPE_EPI>
__global__ __launch_bounds__(256, 1) void gemm_hmma(
    const __half* __restrict__ A, const __half* __restrict__ B,
    float* __restrict__ C, int N,
    const float* __restrict__ cosb, const float* __restrict__ sinb) {
    extern __shared__ __align__(1024) char smem[];
    const uint32_t sbase = smem_u32(smem);
    const int tid = threadIdx.x;
    const int wid = tid >> 5, lane = tid & 31;
    const int bm = blockIdx.y * 256, bn = blockIdx.x * 128;
    const int warp_m = wid & 3, warp_n = wid >> 2;   // 4 x 2, warp tile 64x64

    auto load_chunk = [&](int chunk, int stage) {
        const uint32_t sA = sbase + stage * GSTG;
        const uint32_t sB = sA + 32768;
#pragma unroll
        for (int i = 0; i < 8; i++) {                 // A: 256 rows x 8 c16
            int id = i * 256 + tid;
            int row = id >> 3, c16 = id & 7;
            uint32_t off = (uint32_t)(row * 128 + ((c16 ^ (row & 7)) << 4));
            cp16(sA + off, A + (size_t)(bm + row) * EMB + chunk * GBK + c16 * 8);
        }
#pragma unroll
        for (int i = 0; i < 4; i++) {                 // B: 128 rows x 8 c16
            int id = i * 256 + tid;
            int row = id >> 3, c16 = id & 7;
            uint32_t off = (uint32_t)(row * 128 + ((c16 ^ (row & 7)) << 4));
            cp16(sB + off, B + (size_t)(bn + row) * EMB + chunk * GBK + c16 * 8);
        }
        asm volatile("cp.async.commit_group;" ::: "memory");
    };

    float acc[4][8][4];
#pragma unroll
    for (int mf = 0; mf < 4; mf++)
#pragma unroll
        for (int nf = 0; nf < 8; nf++)
#pragma unroll
            for (int q = 0; q < 4; q++) acc[mf][nf][q] = 0.f;

    load_chunk(0, 0);
    load_chunk(1, 1);

    for (int c = 0; c < NCH; c++) {
        asm volatile("cp.async.wait_group 1;" ::: "memory");
        __syncthreads();
        if (c + 2 < NCH) load_chunk(c + 2, (c + 2) % 3);
        else asm volatile("cp.async.commit_group;" ::: "memory");

        const uint32_t sA = sbase + (c % 3) * GSTG;
        const uint32_t sB = sA + 32768;
#pragma unroll
        for (int kf = 0; kf < 4; kf++) {
            uint32_t afr[4][4];
#pragma unroll
            for (int mf = 0; mf < 4; mf++) {
                int row = warp_m * 64 + mf * 16 + (lane & 15);
                int c16 = kf * 2 + (lane >> 4);
                ldsm_x4(sA + row * 128 + ((c16 ^ (row & 7)) << 4), afr[mf]);
            }
            uint32_t bfr[4][4];
#pragma unroll
            for (int nf2 = 0; nf2 < 4; nf2++) {
                int nrow = warp_n * 64 + nf2 * 16 + ((lane >> 4) << 3) + (lane & 7);
                int c16 = kf * 2 + ((lane >> 3) & 1);
                ldsm_x4(sB + nrow * 128 + ((c16 ^ (nrow & 7)) << 4), bfr[nf2]);
            }
#pragma unroll
            for (int mf = 0; mf < 4; mf++)
#pragma unroll
                for (int nf2 = 0; nf2 < 4; nf2++) {
                    mma_f16(acc[mf][2 * nf2],     afr[mf], &bfr[nf2][0]);
                    mma_f16(acc[mf][2 * nf2 + 1], afr[mf], &bfr[nf2][2]);
                }
        }
    }

    if (ROPE_EPI == 0) {
#pragma unroll
        for (int mf = 0; mf < 4; mf++) {
            int row = bm + warp_m * 64 + mf * 16 + (lane >> 2);
#pragma unroll
            for (int nf = 0; nf < 8; nf++) {
                int col = bn + warp_n * 64 + nf * 8 + (lane & 3) * 2;
                *(float2*)(C + (size_t)row * N + col)       = make_float2(acc[mf][nf][0], acc[mf][nf][1]);
                *(float2*)(C + (size_t)(row + 8) * N + col) = make_float2(acc[mf][nf][2], acc[mf][nf][3]);
            }
        }
    } else {
        // fused rope + scatter. Warp's 64-col tile = one head slot.
        int hidx = (bn >> 6) + warp_n;          // g*6 + slot
        int g = hidx / 6, slot = hidx % 6;
#pragma unroll
        for (int mf = 0; mf < 4; mf++) {
#pragma unroll
            for (int rr = 0; rr < 2; rr++) {
                int row = bm + warp_m * 64 + mf * 16 + (lane >> 2) + rr * 8;
                int b = row >> 11, t = row & (T_SEQ - 1);
#pragma unroll
                for (int nf = 0; nf < 4; nf++) {
                    int d = nf * 8 + (lane & 3) * 2;
                    float x1a = acc[mf][nf][2 * rr],     x1b = acc[mf][nf][2 * rr + 1];
                    float x2a = acc[mf][nf + 4][2 * rr], x2b = acc[mf][nf + 4][2 * rr + 1];
                    if (slot == 5) {
                        __half* dst = g_vh + ((size_t)(b * NG + g) * T_SEQ + t) * HD;
                        *(__half2*)(dst + d)      = __floats2half2_rn(x1a, x1b);
                        *(__half2*)(dst + d + 32) = __floats2half2_rn(x2a, x2b);
                    } else {
                        float2 cc = *(const float2*)(cosb + t * 32 + d);
                        float2 ss = *(const float2*)(sinb + t * 32 + d);
                        float y1a = x1a * cc.x - x2a * ss.x;
                        float y1b = x1b * cc.y - x2b * ss.y;
                        float y2a = x2a * cc.x + x1a * ss.x;
                        float y2b = x2b * cc.y + x1b * ss.y;
                        if (slot == 4) {
                            __half* dst = g_kh + ((size_t)(b * NG + g) * T_SEQ + t) * HD;
                            *(__half2*)(dst + d)      = __floats2half2_rn(y1a, y1b);
                            *(__half2*)(dst + d + 32) = __floats2half2_rn(y2a, y2b);
                        } else {
                            size_t o = ((size_t)(b * NH + g * 4 + slot) * T_SEQ + t) * HD;
                            __half2 h1 = __floats2half2_rn(y1a, y1b);
                            __half2 h2 = __floats2half2_rn(y2a, y2b);
                            *(__half2*)(g_qh + o + d)      = h1;
                            *(__half2*)(g_qh + o + d + 32) = h2;
                            float2 f1 = __half22float2(h1), f2 = __half22float2(h2);
                            *(__half2*)(g_ql + o + d)      = __floats2half2_rn(y1a - f1.x, y1b - f1.y);
                            *(__half2*)(g_ql + o + d + 32) = __floats2half2_rn(y2a - f2.x, y2b - f2.y);
                        }
                    }
                }
            }
        }
    }
}

// ---------------- HMMA flash attention (fp16, q hi/lo split, non-causal) ----------------
#define ABR 128
#define ABC 64
#define ATT_SMEM (32768 + 2 * 16384)
__global__ __launch_bounds__(256, 1) void attn_hmma() {
    extern __shared__ __align__(1024) char smem[];
    const uint32_t sb = smem_u32(smem);
    const uint32_t Qs = sb;            // [128 rows][256B]  (hi c16 0-7 | lo c16 8-15)
    const uint32_t KVs = sb + 32768;   // 2 stages x (K 8192 + V 8192)

    const int tid = threadIdx.x;
    const int w = tid >> 5, lane = tid & 31;
    const int qt = blockIdx.x, bh = blockIdx.y;
    const int b = bh >> 5, h = bh & 31, g = h >> 2;
    const int q0 = qt * ABR;

    const __half* qhb = g_qh + ((size_t)(b * NH + h) * T_SEQ + q0) * HD;
    const __half* qlb = g_ql + ((size_t)(b * NH + h) * T_SEQ + q0) * HD;
    const __half* khb = g_kh + (size_t)(b * NG + g) * T_SEQ * HD;
    const __half* vhb = g_vh + (size_t)(b * NG + g) * T_SEQ * HD;

#pragma unroll
    for (int i = 0; i < 8; i++) {
        int id = i * 256 + tid;
        int row = id >> 4, c16 = id & 15;
        uint32_t off = (uint32_t)(row * 256 + ((((c16 ^ row) & 7) | (c16 & 8)) << 4));
        const __half* src = (c16 < 8) ? (qhb + row * 64 + c16 * 8)
                                      : (qlb + row * 64 + (c16 - 8) * 8);
        cp16(Qs + off, src);
    }
    asm volatile("cp.async.commit_group;" ::: "memory");

    auto loadKV = [&](int t, int s) {
        uint32_t base = KVs + s * 16384;
#pragma unroll
        for (int i = 0; i < 2; i++) {
            int id = i * 256 + tid;
            int row = id >> 3, c8 = id & 7;
            uint32_t off = (uint32_t)(row * 128 + ((c8 ^ (row & 7)) << 4));
            size_t ga = (size_t)(t * ABC + row) * 64 + c8 * 8;
            cp16(base + off, khb + ga);
            cp16(base + 8192 + off, vhb + ga);
        }
        asm volatile("cp.async.commit_group;" ::: "memory");
    };
    loadKV(0, 0);

    float oacc[8][4];
#pragma unroll
    for (int nf = 0; nf < 8; nf++)
#pragma unroll
        for (int q = 0; q < 4; q++) oacc[nf][q] = 0.f;
    float m0 = -1e30f, m1 = -1e30f, l0 = 0.f, l1 = 0.f;
    const float sc = 0.125f;

    const int NT = T_SEQ / ABC;
    for (int t = 0; t < NT; t++) {
        if (t + 1 < NT) { loadKV(t + 1, (t + 1) & 1); asm volatile("cp.async.wait_group 1;" ::: "memory"); }
        else            { asm volatile("cp.async.wait_group 0;" ::: "memory"); }
        __syncthreads();
        const uint32_t kb = KVs + (t & 1) * 16384;
        const uint32_t vb = kb + 8192;

        float sacc[8][4];
#pragma unroll
        for (int nf = 0; nf < 8; nf++)
#pragma unroll
            for (int q = 0; q < 4; q++) sacc[nf][q] = 0.f;

#pragma unroll
        for (int kf = 0; kf < 4; kf++) {
            uint32_t ah[4], al[4];
            {
                int row = w * 16 + (lane & 15);
                int c16h = kf * 2 + (lane >> 4);
                int c16l = 8 + kf * 2 + (lane >> 4);
                ldsm_x4(Qs + row * 256 + ((((c16h ^ row) & 7) | (c16h & 8)) << 4), ah);
                ldsm_x4(Qs + row * 256 + ((((c16l ^ row) & 7) | (c16l & 8)) << 4), al);
            }
#pragma unroll
            for (int nf = 0; nf < 8; nf++) {
                uint32_t bk[2];
                int nrow = nf * 8 + (lane & 7);
                int c8 = kf * 2 + ((lane >> 3) & 1);
                ldsm_x2(kb + nrow * 128 + ((c8 ^ (nrow & 7)) << 4), bk);
                mma_f16(sacc[nf], ah, bk);
                mma_f16(sacc[nf], al, bk);
            }
        }

        float mx0 = -1e30f, mx1 = -1e30f;
#pragma unroll
        for (int nf = 0; nf < 8; nf++) {
            mx0 = fmaxf(mx0, fmaxf(sacc[nf][0], sacc[nf][1]));
            mx1 = fmaxf(mx1, fmaxf(sacc[nf][2], sacc[nf][3]));
        }
        mx0 = fmaxf(mx0, __shfl_xor_sync(0xffffffff, mx0, 1));
        mx0 = fmaxf(mx0, __shfl_xor_sync(0xffffffff, mx0, 2));
        mx1 = fmaxf(mx1, __shfl_xor_sync(0xffffffff, mx1, 1));
        mx1 = fmaxf(mx1, __shfl_xor_sync(0xffffffff, mx1, 2));
        float mn0 = fmaxf(m0, mx0 * sc);
        float mn1 = fmaxf(m1, mx1 * sc);
        float a0 = __expf(m0 - mn0), a1 = __expf(m1 - mn1);
        m0 = mn0; m1 = mn1;

        uint32_t pa[16];
        float s0 = 0.f, s1 = 0.f;
#pragma unroll
        for (int nf = 0; nf < 8; nf++) {
            float p0 = __expf(sacc[nf][0] * sc - mn0);
            float p1 = __expf(sacc[nf][1] * sc - mn0);
            float p2 = __expf(sacc[nf][2] * sc - mn1);
            float p3 = __expf(sacc[nf][3] * sc - mn1);
            s0 += p0 + p1; s1 += p2 + p3;
            __half2 h01 = __floats2half2_rn(p0, p1);
            __half2 h23 = __floats2half2_rn(p2, p3);
            pa[2 * nf]     = *(uint32_t*)&h01;
            pa[2 * nf + 1] = *(uint32_t*)&h23;
        }
        l0 = l0 * a0 + s0;
        l1 = l1 * a1 + s1;
#pragma unroll
        for (int nf = 0; nf < 8; nf++) {
            oacc[nf][0] *= a0; oacc[nf][1] *= a0;
            oacc[nf][2] *= a1; oacc[nf][3] *= a1;
        }

#pragma unroll
        for (int kf2 = 0; kf2 < 4; kf2++) {
            uint32_t a[4] = { pa[4 * kf2], pa[4 * kf2 + 1], pa[4 * kf2 + 2], pa[4 * kf2 + 3] };
#pragma unroll
            for (int nf = 0; nf < 8; nf++) {
                uint32_t bv[2];
                int vrow = kf2 * 16 + (lane & 15);
                int c8 = nf;
                ldsm_x2t(vb + vrow * 128 + ((c8 ^ (vrow & 7)) << 4), bv);
                mma_f16(oacc[nf], a, bv);
            }
        }
        __syncthreads();
    }

    l0 += __shfl_xor_sync(0xffffffff, l0, 1);
    l0 += __shfl_xor_sync(0xffffffff, l0, 2);
    l1 += __shfl_xor_sync(0xffffffff, l1, 1);
    l1 += __shfl_xor_sync(0xffffffff, l1, 2);
    float inv0 = 1.f / l0, inv1 = 1.f / l1;

    int r0 = lane >> 2;
    size_t row0 = (size_t)(b * T_SEQ + q0 + w * 16 + r0) * EMB;
    size_t row1 = row0 + 8 * EMB;
#pragma unroll
    for (int nf = 0; nf < 8; nf++) {
        int col = h * 64 + nf * 8 + (lane & 3) * 2;
        __half2 o01 = __floats2half2_rn(oacc[nf][0] * inv0, oacc[nf][1] * inv0);
        __half2 o23 = __floats2half2_rn(oacc[nf][2] * inv1, oacc[nf][3] * inv1);
        *(__half2*)(g_atth + row0 + col) = o01;
        *(__half2*)(g_atth + row1 + col) = o23;
    }
}

// ---------------- launch ----------------
extern "C" void kernel_launch(void* const* d_in, const int* in_sizes, int n_in,
                              void* d_out, int out_size) {
    const float* x      = (const float*)d_in[0];
    const float* cosb   = (const float*)d_in[1];
    const float* sinb   = (const float*)d_in[2];
    const float* attn_w = (const float*)d_in[3];
    const float* proj_w = (const float*)d_in[4];
    float* out = (float*)d_out;

    __half *xh, *w1h, *w2h, *atth;
    cudaGetSymbolAddress((void**)&xh, g_xh);
    cudaGetSymbolAddress((void**)&w1h, g_w1h);
    cudaGetSymbolAddress((void**)&w2h, g_w2h);
    cudaGetSymbolAddress((void**)&atth, g_atth);

    cudaFuncSetAttribute(gemm_hmma<0>, cudaFuncAttributeMaxDynamicSharedMemorySize, GEMM_SMEM);
    cudaFuncSetAttribute(gemm_hmma<1>, cudaFuncAttributeMaxDynamicSharedMemorySize, GEMM_SMEM);
    cudaFuncSetAttribute(attn_hmma, cudaFuncAttributeMaxDynamicSharedMemorySize, ATT_SMEM);

    // convert inputs to fp16
    {
        int n4 = BT_TOTAL * EMB / 4;
        to_half<<<(n4 + 255) / 256, 256>>>(x, xh, n4);
        n4 = FD * EMB / 4;
        to_half<<<(n4 + 255) / 256, 256>>>(attn_w, w1h, n4);
        n4 = EMB * EMB / 4;
        to_half<<<(n4 + 255) / 256, 256>>>(proj_w, w2h, n4);
    }

    // 1) qkv = x @ attn_w^T with fused rope + scatter to fp16 q(hi/lo)/k/v
    gemm_hmma<1><<<dim3(FD / 128, BT_TOTAL / 256), 256, GEMM_SMEM>>>(
        xh, w1h, nullptr, FD, cosb, sinb);

    // 2) HMMA flash attention -> g_atth (fp16)
    attn_hmma<<<dim3(T_SEQ / ABR, 2 * NH), 256, ATT_SMEM>>>();

    // 3) out = att @ proj_w^T (fp32 out)
    gemm_hmma<0><<<dim3(EMB / 128, BT_TOTAL / 256), 256, GEMM_SMEM>>>(
        atth, w2h, out, EMB, nullptr, nullptr);
}

// round 15
// speedup vs baseline: 1.6801x; 1.1065x over previous
#include <cuda_runtime.h>
#include <cuda_fp16.h>
#include <cstdint>

#define BT_TOTAL 4096
#define T_SEQ    2048
#define EMB      2048
#define FD       3072
#define NH       32
#define NG       8
#define HD       64
#define GBK      64
#define NCH      (EMB / GBK)    // 32

// ---------------- device scratch (no allocations allowed) ----------------
__device__ __half g_qh[(size_t)2 * NH * T_SEQ * HD];
__device__ __half g_kh[(size_t)2 * NG * T_SEQ * HD];
__device__ __half g_vh[(size_t)2 * NG * T_SEQ * HD];

__device__ __half g_xh[(size_t)BT_TOTAL * EMB];
__device__ __half g_w1h[(size_t)FD * EMB];
__device__ __half g_w2h[(size_t)EMB * EMB];
__device__ __half g_atth[(size_t)BT_TOTAL * EMB];

// ---------------- helpers ----------------
__device__ __forceinline__ uint32_t smem_u32(const void* p) {
    uint32_t a;
    asm("{ .reg .u64 t; cvta.to.shared.u64 t, %1; cvt.u32.u64 %0, t; }" : "=r"(a) : "l"(p));
    return a;
}
__device__ __forceinline__ void cp16(uint32_t dst, const void* src) {
    asm volatile("cp.async.cg.shared.global [%0], [%1], 16;" :: "r"(dst), "l"(src));
}
__device__ __forceinline__ void ldsm_x4(uint32_t addr, uint32_t* r) {
    asm volatile("ldmatrix.sync.aligned.m8n8.x4.shared.b16 {%0,%1,%2,%3}, [%4];"
        : "=r"(r[0]), "=r"(r[1]), "=r"(r[2]), "=r"(r[3]) : "r"(addr));
}
__device__ __forceinline__ void ldsm_x2t(uint32_t addr, uint32_t* r) {
    asm volatile("ldmatrix.sync.aligned.m8n8.x2.trans.shared.b16 {%0,%1}, [%2];"
        : "=r"(r[0]), "=r"(r[1]) : "r"(addr));
}
__device__ __forceinline__ void mma_f16(float* c, const uint32_t* a, const uint32_t* b) {
    asm volatile("mma.sync.aligned.m16n8k16.row.col.f32.f16.f16.f32 "
        "{%0,%1,%2,%3}, {%4,%5,%6,%7}, {%8,%9}, {%0,%1,%2,%3};"
        : "+f"(c[0]), "+f"(c[1]), "+f"(c[2]), "+f"(c[3])
        : "r"(a[0]), "r"(a[1]), "r"(a[2]), "r"(a[3]), "r"(b[0]), "r"(b[1]));
}

// ---------------- convert fp32 -> fp16 ----------------
__global__ void to_half(const float* __restrict__ src, __half* __restrict__ dst, int n4) {
    int i = blockIdx.x * blockDim.x + threadIdx.x;
    if (i >= n4) return;
    float4 v = *(const float4*)(src + (size_t)i * 4);
    __half2 a = __floats2half2_rn(v.x, v.y);
    __half2 b = __floats2half2_rn(v.z, v.w);
    ((__half2*)dst)[i * 2]     = a;
    ((__half2*)dst)[i * 2 + 1] = b;
}

// ---------------- fp16 HMMA GEMM: 256 threads, tile 256x128, warp 64x64 (4x2) --------
// ROPE_EPI=0: C[M,N] fp32 plain store.  ROPE_EPI=1: fused rope+scatter to q/k/v fp16.
#define GSTG 49152                      // A 32KB + B 16KB per stage
#define GEMM_SMEM (3 * GSTG)
template <int ROPE_EPI>
__global__ __launch_bounds__(256, 1) void gemm_hmma(
    const __half* __restrict__ A, const __half* __restrict__ B,
    float* __restrict__ C, int N,
    const float* __restrict__ cosb, const float* __restrict__ sinb) {
    extern __shared__ __align__(1024) char smem[];
    const uint32_t sbase = smem_u32(smem);
    const int tid = threadIdx.x;
    const int wid = tid >> 5, lane = tid & 31;
    const int bm = blockIdx.y * 256, bn = blockIdx.x * 128;
    const int warp_m = wid & 3, warp_n = wid >> 2;   // 4 x 2, warp tile 64x64

    auto load_chunk = [&](int chunk, int stage) {
        const uint32_t sA = sbase + stage * GSTG;
        const uint32_t sB = sA + 32768;
#pragma unroll
        for (int i = 0; i < 8; i++) {                 // A: 256 rows x 8 c16
            int id = i * 256 + tid;
            int row = id >> 3, c16 = id & 7;
            uint32_t off = (uint32_t)(row * 128 + ((c16 ^ (row & 7)) << 4));
            cp16(sA + off, A + (size_t)(bm + row) * EMB + chunk * GBK + c16 * 8);
        }
#pragma unroll
        for (int i = 0; i < 4; i++) {                 // B: 128 rows x 8 c16
            int id = i * 256 + tid;
            int row = id >> 3, c16 = id & 7;
            uint32_t off = (uint32_t)(row * 128 + ((c16 ^ (row & 7)) << 4));
            cp16(sB + off, B + (size_t)(bn + row) * EMB + chunk * GBK + c16 * 8);
        }
        asm volatile("cp.async.commit_group;" ::: "memory");
    };

    float acc[4][8][4];
#pragma unroll
    for (int mf = 0; mf < 4; mf++)
#pragma unroll
        for (int nf = 0; nf < 8; nf++)
#pragma unroll
            for (int q = 0; q < 4; q++) acc[mf][nf][q] = 0.f;

    load_chunk(0, 0);
    load_chunk(1, 1);

    for (int c = 0; c < NCH; c++) {
        asm volatile("cp.async.wait_group 1;" ::: "memory");
        __syncthreads();
        if (c + 2 < NCH) load_chunk(c + 2, (c + 2) % 3);
        else asm volatile("cp.async.commit_group;" ::: "memory");

        const uint32_t sA = sbase + (c % 3) * GSTG;
        const uint32_t sB = sA + 32768;
#pragma unroll
        for (int kf = 0; kf < 4; kf++) {
            uint32_t afr[4][4];
#pragma unroll
            for (int mf = 0; mf < 4; mf++) {
                int row = warp_m * 64 + mf * 16 + (lane & 15);
                int c16 = kf * 2 + (lane >> 4);
                ldsm_x4(sA + row * 128 + ((c16 ^ (row & 7)) << 4), afr[mf]);
            }
            uint32_t bfr[4][4];
#pragma unroll
            for (int nf2 = 0; nf2 < 4; nf2++) {
                int nrow = warp_n * 64 + nf2 * 16 + ((lane >> 4) << 3) + (lane & 7);
                int c16 = kf * 2 + ((lane >> 3) & 1);
                ldsm_x4(sB + nrow * 128 + ((c16 ^ (nrow & 7)) << 4), bfr[nf2]);
            }
#pragma unroll
            for (int mf = 0; mf < 4; mf++)
#pragma unroll
                for (int nf2 = 0; nf2 < 4; nf2++) {
                    mma_f16(acc[mf][2 * nf2],     afr[mf], &bfr[nf2][0]);
                    mma_f16(acc[mf][2 * nf2 + 1], afr[mf], &bfr[nf2][2]);
                }
        }
    }

    if (ROPE_EPI == 0) {
#pragma unroll
        for (int mf = 0; mf < 4; mf++) {
            int row = bm + warp_m * 64 + mf * 16 + (lane >> 2);
#pragma unroll
            for (int nf = 0; nf < 8; nf++) {
                int col = bn + warp_n * 64 + nf * 8 + (lane & 3) * 2;
                *(float2*)(C + (size_t)row * N + col)       = make_float2(acc[mf][nf][0], acc[mf][nf][1]);
                *(float2*)(C + (size_t)(row + 8) * N + col) = make_float2(acc[mf][nf][2], acc[mf][nf][3]);
            }
        }
    } else {
        // fused rope + scatter. Warp's 64-col tile = one head slot.
        int hidx = (bn >> 6) + warp_n;          // g*6 + slot
        int g = hidx / 6, slot = hidx % 6;
#pragma unroll
        for (int mf = 0; mf < 4; mf++) {
#pragma unroll
            for (int rr = 0; rr < 2; rr++) {
                int row = bm + warp_m * 64 + mf * 16 + (lane >> 2) + rr * 8;
                int b = row >> 11, t = row & (T_SEQ - 1);
#pragma unroll
                for (int nf = 0; nf < 4; nf++) {
                    int d = nf * 8 + (lane & 3) * 2;
                    float x1a = acc[mf][nf][2 * rr],     x1b = acc[mf][nf][2 * rr + 1];
                    float x2a = acc[mf][nf + 4][2 * rr], x2b = acc[mf][nf + 4][2 * rr + 1];
                    if (slot == 5) {
                        __half* dst = g_vh + ((size_t)(b * NG + g) * T_SEQ + t) * HD;
                        *(__half2*)(dst + d)      = __floats2half2_rn(x1a, x1b);
                        *(__half2*)(dst + d + 32) = __floats2half2_rn(x2a, x2b);
                    } else {
                        float2 cc = *(const float2*)(cosb + t * 32 + d);
                        float2 ss = *(const float2*)(sinb + t * 32 + d);
                        float y1a = x1a * cc.x - x2a * ss.x;
                        float y1b = x1b * cc.y - x2b * ss.y;
                        float y2a = x2a * cc.x + x1a * ss.x;
                        float y2b = x2b * cc.y + x1b * ss.y;
                        __half* dst = (slot == 4)
                            ? g_kh + ((size_t)(b * NG + g) * T_SEQ + t) * HD
                            : g_qh + ((size_t)(b * NH + g * 4 + slot) * T_SEQ + t) * HD;
                        *(__half2*)(dst + d)      = __floats2half2_rn(y1a, y1b);
                        *(__half2*)(dst + d + 32) = __floats2half2_rn(y2a, y2b);
                    }
                }
            }
        }
    }
}

// ---------------- HMMA flash attention (fp16, non-causal) ----------------
// Br=128, Bc=64, 256 threads (8 warps x 16 q rows).
#define ABR 128
#define ABC 64
#define ATT_SMEM (16384 + 2 * 16384)
__global__ __launch_bounds__(256, 1) void attn_hmma() {
    extern __shared__ __align__(1024) char smem[];
    const uint32_t sb = smem_u32(smem);
    const uint32_t Qs = sb;            // [128 rows][128B]
    const uint32_t KVs = sb + 16384;   // 2 stages x (K 8192 + V 8192)

    const int tid = threadIdx.x;
    const int w = tid >> 5, lane = tid & 31;
    const int qt = blockIdx.x, bh = blockIdx.y;
    const int b = bh >> 5, h = bh & 31, g = h >> 2;
    const int q0 = qt * ABR;

    const __half* qhb = g_qh + ((size_t)(b * NH + h) * T_SEQ + q0) * HD;
    const __half* khb = g_kh + (size_t)(b * NG + g) * T_SEQ * HD;
    const __half* vhb = g_vh + (size_t)(b * NG + g) * T_SEQ * HD;

    // Q load: 128 rows x 8 chunks of 16B
#pragma unroll
    for (int i = 0; i < 4; i++) {
        int id = i * 256 + tid;
        int row = id >> 3, c8 = id & 7;
        uint32_t off = (uint32_t)(row * 128 + ((c8 ^ (row & 7)) << 4));
        cp16(Qs + off, qhb + row * 64 + c8 * 8);
    }
    asm volatile("cp.async.commit_group;" ::: "memory");

    auto loadKV = [&](int t, int s) {
        uint32_t base = KVs + s * 16384;
#pragma unroll
        for (int i = 0; i < 2; i++) {
            int id = i * 256 + tid;
            int row = id >> 3, c8 = id & 7;
            uint32_t off = (uint32_t)(row * 128 + ((c8 ^ (row & 7)) << 4));
            size_t ga = (size_t)(t * ABC + row) * 64 + c8 * 8;
            cp16(base + off, khb + ga);
            cp16(base + 8192 + off, vhb + ga);
        }
        asm volatile("cp.async.commit_group;" ::: "memory");
    };
    loadKV(0, 0);

    float oacc[8][4];
#pragma unroll
    for (int nf = 0; nf < 8; nf++)
#pragma unroll
        for (int q = 0; q < 4; q++) oacc[nf][q] = 0.f;
    float m0 = -1e30f, m1 = -1e30f, l0 = 0.f, l1 = 0.f;
    const float sc = 0.125f;

    const int NT = T_SEQ / ABC;
    for (int t = 0; t < NT; t++) {
        if (t + 1 < NT) { loadKV(t + 1, (t + 1) & 1); asm volatile("cp.async.wait_group 1;" ::: "memory"); }
        else            { asm volatile("cp.async.wait_group 0;" ::: "memory"); }
        __syncthreads();
        const uint32_t kb = KVs + (t & 1) * 16384;
        const uint32_t vb = kb + 8192;

        // ---- S = Q @ K^T
        float sacc[8][4];
#pragma unroll
        for (int nf = 0; nf < 8; nf++)
#pragma unroll
            for (int q = 0; q < 4; q++) sacc[nf][q] = 0.f;

#pragma unroll
        for (int kf = 0; kf < 4; kf++) {
            uint32_t ah[4];
            {
                int row = w * 16 + (lane & 15);
                int c16 = kf * 2 + (lane >> 4);
                ldsm_x4(Qs + row * 128 + ((c16 ^ (row & 7)) << 4), ah);
            }
#pragma unroll
            for (int nf2 = 0; nf2 < 4; nf2++) {
                uint32_t bk[4];
                int nrow = nf2 * 16 + ((lane >> 4) << 3) + (lane & 7);
                int c8 = kf * 2 + ((lane >> 3) & 1);
                ldsm_x4(kb + nrow * 128 + ((c8 ^ (nrow & 7)) << 4), bk);
                mma_f16(sacc[2 * nf2],     ah, &bk[0]);
                mma_f16(sacc[2 * nf2 + 1], ah, &bk[2]);
            }
        }

        // ---- online softmax
        float mx0 = -1e30f, mx1 = -1e30f;
#pragma unroll
        for (int nf = 0; nf < 8; nf++) {
            mx0 = fmaxf(mx0, fmaxf(sacc[nf][0], sacc[nf][1]));
            mx1 = fmaxf(mx1, fmaxf(sacc[nf][2], sacc[nf][3]));
        }
        mx0 = fmaxf(mx0, __shfl_xor_sync(0xffffffff, mx0, 1));
        mx0 = fmaxf(mx0, __shfl_xor_sync(0xffffffff, mx0, 2));
        mx1 = fmaxf(mx1, __shfl_xor_sync(0xffffffff, mx1, 1));
        mx1 = fmaxf(mx1, __shfl_xor_sync(0xffffffff, mx1, 2));
        float mn0 = fmaxf(m0, mx0 * sc);
        float mn1 = fmaxf(m1, mx1 * sc);
        float a0 = __expf(m0 - mn0), a1 = __expf(m1 - mn1);
        m0 = mn0; m1 = mn1;

        uint32_t pa[16];
        float s0 = 0.f, s1 = 0.f;
#pragma unroll
        for (int nf = 0; nf < 8; nf++) {
            float p0 = __expf(sacc[nf][0] * sc - mn0);
            float p1 = __expf(sacc[nf][1] * sc - mn0);
            float p2 = __expf(sacc[nf][2] * sc - mn1);
            float p3 = __expf(sacc[nf][3] * sc - mn1);
            s0 += p0 + p1; s1 += p2 + p3;
            __half2 h01 = __floats2half2_rn(p0, p1);
            __half2 h23 = __floats2half2_rn(p2, p3);
            pa[2 * nf]     = *(uint32_t*)&h01;
            pa[2 * nf + 1] = *(uint32_t*)&h23;
        }
        l0 = l0 * a0 + s0;
        l1 = l1 * a1 + s1;
#pragma unroll
        for (int nf = 0; nf < 8; nf++) {
            oacc[nf][0] *= a0; oacc[nf][1] *= a0;
            oacc[nf][2] *= a1; oacc[nf][3] *= a1;
        }

        // ---- O += P @ V   (V via ldmatrix.trans: [key][d] storage)
#pragma unroll
        for (int kf2 = 0; kf2 < 4; kf2++) {
            uint32_t a[4] = { pa[4 * kf2], pa[4 * kf2 + 1], pa[4 * kf2 + 2], pa[4 * kf2 + 3] };
#pragma unroll
            for (int nf = 0; nf < 8; nf++) {
                uint32_t bv[2];
                int vrow = kf2 * 16 + (lane & 15);
                int c8 = nf;
                ldsm_x2t(vb + vrow * 128 + ((c8 ^ (vrow & 7)) << 4), bv);
                mma_f16(oacc[nf], a, bv);
            }
        }
        __syncthreads();
    }

    l0 += __shfl_xor_sync(0xffffffff, l0, 1);
    l0 += __shfl_xor_sync(0xffffffff, l0, 2);
    l1 += __shfl_xor_sync(0xffffffff, l1, 1);
    l1 += __shfl_xor_sync(0xffffffff, l1, 2);
    float inv0 = 1.f / l0, inv1 = 1.f / l1;

    int r0 = lane >> 2;
    size_t row0 = (size_t)(b * T_SEQ + q0 + w * 16 + r0) * EMB;
    size_t row1 = row0 + 8 * EMB;
#pragma unroll
    for (int nf = 0; nf < 8; nf++) {
        int col = h * 64 + nf * 8 + (lane & 3) * 2;
        __half2 o01 = __floats2half2_rn(oacc[nf][0] * inv0, oacc[nf][1] * inv0);
        __half2 o23 = __floats2half2_rn(oacc[nf][2] * inv1, oacc[nf][3] * inv1);
        *(__half2*)(g_atth + row0 + col) = o01;
        *(__half2*)(g_atth + row1 + col) = o23;
    }
}

// ---------------- launch ----------------
extern "C" void kernel_launch(void* const* d_in, const int* in_sizes, int n_in,
                              void* d_out, int out_size) {
    const float* x      = (const float*)d_in[0];
    const float* cosb   = (const float*)d_in[1];
    const float* sinb   = (const float*)d_in[2];
    const float* attn_w = (const float*)d_in[3];
    const float* proj_w = (const float*)d_in[4];
    float* out = (float*)d_out;

    __half *xh, *w1h, *w2h, *atth;
    cudaGetSymbolAddress((void**)&xh, g_xh);
    cudaGetSymbolAddress((void**)&w1h, g_w1h);
    cudaGetSymbolAddress((void**)&w2h, g_w2h);
    cudaGetSymbolAddress((void**)&atth, g_atth);

    cudaFuncSetAttribute(gemm_hmma<0>, cudaFuncAttributeMaxDynamicSharedMemorySize, GEMM_SMEM);
    cudaFuncSetAttribute(gemm_hmma<1>, cudaFuncAttributeMaxDynamicSharedMemorySize, GEMM_SMEM);
    cudaFuncSetAttribute(attn_hmma, cudaFuncAttributeMaxDynamicSharedMemorySize, ATT_SMEM);

    // convert inputs to fp16
    {
        int n4 = BT_TOTAL * EMB / 4;
        to_half<<<(n4 + 255) / 256, 256>>>(x, xh, n4);
        n4 = FD * EMB / 4;
        to_half<<<(n4 + 255) / 256, 256>>>(attn_w, w1h, n4);
        n4 = EMB * EMB / 4;
        to_half<<<(n4 + 255) / 256, 256>>>(proj_w, w2h, n4);
    }

    // 1) qkv = x @ attn_w^T with fused rope + scatter to fp16 q/k/v
    gemm_hmma<1><<<dim3(FD / 128, BT_TOTAL / 256), 256, GEMM_SMEM>>>(
        xh, w1h, nullptr, FD, cosb, sinb);

    // 2) HMMA flash attention -> g_atth (fp16)
    attn_hmma<<<dim3(T_SEQ / ABR, 2 * NH), 256, ATT_SMEM>>>();

    // 3) out = att @ proj_w^T (fp32 out)
    gemm_hmma<0><<<dim3(EMB / 128, BT_TOTAL / 256), 256, GEMM_SMEM>>>(
        atth, w2h, out, EMB, nullptr, nullptr);
}

// round 16
// speedup vs baseline: 1.7468x; 1.0397x over previous
#include <cuda_runtime.h>
#include <cuda_fp16.h>
#include <cstdint>

#define BT_TOTAL 4096
#define T_SEQ    2048
#define EMB      2048
#define FD       3072
#define NH       32
#define NG       8
#define HD       64
#define GBK      64
#define NCH      (EMB / GBK)    // 32

// ---------------- device scratch (no allocations allowed) ----------------
__device__ __half g_qh[(size_t)2 * NH * T_SEQ * HD];
__device__ __half g_kh[(size_t)2 * NG * T_SEQ * HD];
__device__ __half g_vh[(size_t)2 * NG * T_SEQ * HD];

__device__ __half g_xh[(size_t)BT_TOTAL * EMB];
__device__ __half g_w1h[(size_t)FD * EMB];
__device__ __half g_w2h[(size_t)EMB * EMB];
__device__ __half g_atth[(size_t)BT_TOTAL * EMB];

// ---------------- helpers ----------------
__device__ __forceinline__ uint32_t smem_u32(const void* p) {
    uint32_t a;
    asm("{ .reg .u64 t; cvta.to.shared.u64 t, %1; cvt.u32.u64 %0, t; }" : "=r"(a) : "l"(p));
    return a;
}
__device__ __forceinline__ void cp16(uint32_t dst, const void* src) {
    asm volatile("cp.async.cg.shared.global [%0], [%1], 16;" :: "r"(dst), "l"(src));
}
__device__ __forceinline__ void ldsm_x4(uint32_t addr, uint32_t* r) {
    asm volatile("ldmatrix.sync.aligned.m8n8.x4.shared.b16 {%0,%1,%2,%3}, [%4];"
        : "=r"(r[0]), "=r"(r[1]), "=r"(r[2]), "=r"(r[3]) : "r"(addr));
}
__device__ __forceinline__ void ldsm_x4t(uint32_t addr, uint32_t* r) {
    asm volatile("ldmatrix.sync.aligned.m8n8.x4.trans.shared.b16 {%0,%1,%2,%3}, [%4];"
        : "=r"(r[0]), "=r"(r[1]), "=r"(r[2]), "=r"(r[3]) : "r"(addr));
}
__device__ __forceinline__ void mma_f16(float* c, const uint32_t* a, const uint32_t* b) {
    asm volatile("mma.sync.aligned.m16n8k16.row.col.f32.f16.f16.f32 "
        "{%0,%1,%2,%3}, {%4,%5,%6,%7}, {%8,%9}, {%0,%1,%2,%3};"
        : "+f"(c[0]), "+f"(c[1]), "+f"(c[2]), "+f"(c[3])
        : "r"(a[0]), "r"(a[1]), "r"(a[2]), "r"(a[3]), "r"(b[0]), "r"(b[1]));
}

// ---------------- convert fp32 -> fp16 ----------------
__global__ void to_half(const float* __restrict__ src, __half* __restrict__ dst, int n4) {
    int i = blockIdx.x * blockDim.x + threadIdx.x;
    if (i >= n4) return;
    float4 v = *(const float4*)(src + (size_t)i * 4);
    __half2 a = __floats2half2_rn(v.x, v.y);
    __half2 b = __floats2half2_rn(v.z, v.w);
    ((__half2*)dst)[i * 2]     = a;
    ((__half2*)dst)[i * 2 + 1] = b;
}

// ---------------- fp16 HMMA GEMM: 128 threads, tile 128x128, warp 64x64 (2x2) --------
// 2 CTAs/SM. ROPE_EPI=0: C fp32 store. ROPE_EPI=1: fused rope+scatter to q/k/v fp16.
#define GSTG 32768                      // A 16KB + B 16KB per stage
#define GEMM_SMEM (3 * GSTG)
template <int ROPE_EPI>
__global__ __launch_bounds__(128, 2) void gemm_hmma(
    const __half* __restrict__ A, const __half* __restrict__ B,
    float* __restrict__ C, int N,
    const float* __restrict__ cosb, const float* __restrict__ sinb) {
    extern __shared__ __align__(1024) char smem[];
    const uint32_t sbase = smem_u32(smem);
    const int tid = threadIdx.x;
    const int wid = tid >> 5, lane = tid & 31;
    const int bm = blockIdx.y * 128, bn = blockIdx.x * 128;
    const int warp_m = wid & 1, warp_n = wid >> 1;   // 2 x 2, warp tile 64x64

    auto load_chunk = [&](int chunk, int stage) {
        const uint32_t sA = sbase + stage * GSTG;
        const uint32_t sB = sA + 16384;
#pragma unroll
        for (int i = 0; i < 8; i++) {                 // A: 128 rows x 8 c16
            int id = i * 128 + tid;
            int row = id >> 3, c16 = id & 7;
            uint32_t off = (uint32_t)(row * 128 + ((c16 ^ (row & 7)) << 4));
            cp16(sA + off, A + (size_t)(bm + row) * EMB + chunk * GBK + c16 * 8);
        }
#pragma unroll
        for (int i = 0; i < 8; i++) {                 // B: 128 rows x 8 c16
            int id = i * 128 + tid;
            int row = id >> 3, c16 = id & 7;
            uint32_t off = (uint32_t)(row * 128 + ((c16 ^ (row & 7)) << 4));
            cp16(sB + off, B + (size_t)(bn + row) * EMB + chunk * GBK + c16 * 8);
        }
        asm volatile("cp.async.commit_group;" ::: "memory");
    };

    float acc[4][8][4];
#pragma unroll
    for (int mf = 0; mf < 4; mf++)
#pragma unroll
        for (int nf = 0; nf < 8; nf++)
#pragma unroll
            for (int q = 0; q < 4; q++) acc[mf][nf][q] = 0.f;

    load_chunk(0, 0);
    load_chunk(1, 1);

    for (int c = 0; c < NCH; c++) {
        asm volatile("cp.async.wait_group 1;" ::: "memory");
        __syncthreads();
        if (c + 2 < NCH) load_chunk(c + 2, (c + 2) % 3);
        else asm volatile("cp.async.commit_group;" ::: "memory");

        const uint32_t sA = sbase + (c % 3) * GSTG;
        const uint32_t sB = sA + 16384;
#pragma unroll
        for (int kf = 0; kf < 4; kf++) {
            uint32_t afr[4][4];
#pragma unroll
            for (int mf = 0; mf < 4; mf++) {
                int row = warp_m * 64 + mf * 16 + (lane & 15);
                int c16 = kf * 2 + (lane >> 4);
                ldsm_x4(sA + row * 128 + ((c16 ^ (row & 7)) << 4), afr[mf]);
            }
            uint32_t bfr[4][4];
#pragma unroll
            for (int nf2 = 0; nf2 < 4; nf2++) {
                int nrow = warp_n * 64 + nf2 * 16 + ((lane >> 4) << 3) + (lane & 7);
                int c16 = kf * 2 + ((lane >> 3) & 1);
                ldsm_x4(sB + nrow * 128 + ((c16 ^ (nrow & 7)) << 4), bfr[nf2]);
            }
#pragma unroll
            for (int mf = 0; mf < 4; mf++)
#pragma unroll
                for (int nf2 = 0; nf2 < 4; nf2++) {
                    mma_f16(acc[mf][2 * nf2],     afr[mf], &bfr[nf2][0]);
                    mma_f16(acc[mf][2 * nf2 + 1], afr[mf], &bfr[nf2][2]);
                }
        }
    }

    if (ROPE_EPI == 0) {
#pragma unroll
        for (int mf = 0; mf < 4; mf++) {
            int row = bm + warp_m * 64 + mf * 16 + (lane >> 2);
#pragma unroll
            for (int nf = 0; nf < 8; nf++) {
                int col = bn + warp_n * 64 + nf * 8 + (lane & 3) * 2;
                *(float2*)(C + (size_t)row * N + col)       = make_float2(acc[mf][nf][0], acc[mf][nf][1]);
                *(float2*)(C + (size_t)(row + 8) * N + col) = make_float2(acc[mf][nf][2], acc[mf][nf][3]);
            }
        }
    } else {
        // fused rope + scatter. Warp's 64-col tile = one head slot.
        int hidx = (bn >> 6) + warp_n;          // g*6 + slot
        int g = hidx / 6, slot = hidx % 6;
#pragma unroll
        for (int mf = 0; mf < 4; mf++) {
#pragma unroll
            for (int rr = 0; rr < 2; rr++) {
                int row = bm + warp_m * 64 + mf * 16 + (lane >> 2) + rr * 8;
                int b = row >> 11, t = row & (T_SEQ - 1);
#pragma unroll
                for (int nf = 0; nf < 4; nf++) {
                    int d = nf * 8 + (lane & 3) * 2;
                    float x1a = acc[mf][nf][2 * rr],     x1b = acc[mf][nf][2 * rr + 1];
                    float x2a = acc[mf][nf + 4][2 * rr], x2b = acc[mf][nf + 4][2 * rr + 1];
                    if (slot == 5) {
                        __half* dst = g_vh + ((size_t)(b * NG + g) * T_SEQ + t) * HD;
                        *(__half2*)(dst + d)      = __floats2half2_rn(x1a, x1b);
                        *(__half2*)(dst + d + 32) = __floats2half2_rn(x2a, x2b);
                    } else {
                        float2 cc = *(const float2*)(cosb + t * 32 + d);
                        float2 ss = *(const float2*)(sinb + t * 32 + d);
                        float y1a = x1a * cc.x - x2a * ss.x;
                        float y1b = x1b * cc.y - x2b * ss.y;
                        float y2a = x2a * cc.x + x1a * ss.x;
                        float y2b = x2b * cc.y + x1b * ss.y;
                        __half* dst = (slot == 4)
                            ? g_kh + ((size_t)(b * NG + g) * T_SEQ + t) * HD
                            : g_qh + ((size_t)(b * NH + g * 4 + slot) * T_SEQ + t) * HD;
                        *(__half2*)(dst + d)      = __floats2half2_rn(y1a, y1b);
                        *(__half2*)(dst + d + 32) = __floats2half2_rn(y2a, y2b);
                    }
                }
            }
        }
    }
}

// ---------------- HMMA flash attention (fp16, non-causal) ----------------
// Br=128, Bc=64, 256 threads (8 warps x 16 q rows).
#define ABR 128
#define ABC 64
#define ATT_SMEM (16384 + 2 * 16384)
__global__ __launch_bounds__(256, 1) void attn_hmma() {
    extern __shared__ __align__(1024) char smem[];
    const uint32_t sb = smem_u32(smem);
    const uint32_t Qs = sb;            // [128 rows][128B]
    const uint32_t KVs = sb + 16384;   // 2 stages x (K 8192 + V 8192)

    const int tid = threadIdx.x;
    const int w = tid >> 5, lane = tid & 31;
    const int qt = blockIdx.x, bh = blockIdx.y;
    const int b = bh >> 5, h = bh & 31, g = h >> 2;
    const int q0 = qt * ABR;

    const __half* qhb = g_qh + ((size_t)(b * NH + h) * T_SEQ + q0) * HD;
    const __half* khb = g_kh + (size_t)(b * NG + g) * T_SEQ * HD;
    const __half* vhb = g_vh + (size_t)(b * NG + g) * T_SEQ * HD;

    // Q load: 128 rows x 8 chunks of 16B
#pragma unroll
    for (int i = 0; i < 4; i++) {
        int id = i * 256 + tid;
        int row = id >> 3, c8 = id & 7;
        uint32_t off = (uint32_t)(row * 128 + ((c8 ^ (row & 7)) << 4));
        cp16(Qs + off, qhb + row * 64 + c8 * 8);
    }
    asm volatile("cp.async.commit_group;" ::: "memory");

    auto loadKV = [&](int t, int s) {
        uint32_t base = KVs + s * 16384;
#pragma unroll
        for (int i = 0; i < 2; i++) {
            int id = i * 256 + tid;
            int row = id >> 3, c8 = id & 7;
            uint32_t off = (uint32_t)(row * 128 + ((c8 ^ (row & 7)) << 4));
            size_t ga = (size_t)(t * ABC + row) * 64 + c8 * 8;
            cp16(base + off, khb + ga);
            cp16(base + 8192 + off, vhb + ga);
        }
        asm volatile("cp.async.commit_group;" ::: "memory");
    };
    loadKV(0, 0);

    float oacc[8][4];
#pragma unroll
    for (int nf = 0; nf < 8; nf++)
#pragma unroll
        for (int q = 0; q < 4; q++) oacc[nf][q] = 0.f;
    float m0 = -1e30f, m1 = -1e30f, l0 = 0.f, l1 = 0.f;
    const float sc = 0.125f;

    const int NT = T_SEQ / ABC;
    for (int t = 0; t < NT; t++) {
        if (t + 1 < NT) { loadKV(t + 1, (t + 1) & 1); asm volatile("cp.async.wait_group 1;" ::: "memory"); }
        else            { asm volatile("cp.async.wait_group 0;" ::: "memory"); }
        __syncthreads();
        const uint32_t kb = KVs + (t & 1) * 16384;
        const uint32_t vb = kb + 8192;

        // ---- S = Q @ K^T
        float sacc[8][4];
#pragma unroll
        for (int nf = 0; nf < 8; nf++)
#pragma unroll
            for (int q = 0; q < 4; q++) sacc[nf][q] = 0.f;

#pragma unroll
        for (int kf = 0; kf < 4; kf++) {
            uint32_t ah[4];
            {
                int row = w * 16 + (lane & 15);
                int c16 = kf * 2 + (lane >> 4);
                ldsm_x4(Qs + row * 128 + ((c16 ^ (row & 7)) << 4), ah);
            }
#pragma unroll
            for (int nf2 = 0; nf2 < 4; nf2++) {
                uint32_t bk[4];
                int nrow = nf2 * 16 + ((lane >> 4) << 3) + (lane & 7);
                int c8 = kf * 2 + ((lane >> 3) & 1);
                ldsm_x4(kb + nrow * 128 + ((c8 ^ (nrow & 7)) << 4), bk);
                mma_f16(sacc[2 * nf2],     ah, &bk[0]);
                mma_f16(sacc[2 * nf2 + 1], ah, &bk[2]);
            }
        }

        // ---- online softmax
        float mx0 = -1e30f, mx1 = -1e30f;
#pragma unroll
        for (int nf = 0; nf < 8; nf++) {
            mx0 = fmaxf(mx0, fmaxf(sacc[nf][0], sacc[nf][1]));
            mx1 = fmaxf(mx1, fmaxf(sacc[nf][2], sacc[nf][3]));
        }
        mx0 = fmaxf(mx0, __shfl_xor_sync(0xffffffff, mx0, 1));
        mx0 = fmaxf(mx0, __shfl_xor_sync(0xffffffff, mx0, 2));
        mx1 = fmaxf(mx1, __shfl_xor_sync(0xffffffff, mx1, 1));
        mx1 = fmaxf(mx1, __shfl_xor_sync(0xffffffff, mx1, 2));
        float mn0 = fmaxf(m0, mx0 * sc);
        float mn1 = fmaxf(m1, mx1 * sc);
        float a0 = __expf(m0 - mn0), a1 = __expf(m1 - mn1);
        m0 = mn0; m1 = mn1;

        uint32_t pa[16];
        float s0 = 0.f, s1 = 0.f;
#pragma unroll
        for (int nf = 0; nf < 8; nf++) {
            float p0 = __expf(sacc[nf][0] * sc - mn0);
            float p1 = __expf(sacc[nf][1] * sc - mn0);
            float p2 = __expf(sacc[nf][2] * sc - mn1);
            float p3 = __expf(sacc[nf][3] * sc - mn1);
            s0 += p0 + p1; s1 += p2 + p3;
            __half2 h01 = __floats2half2_rn(p0, p1);
            __half2 h23 = __floats2half2_rn(p2, p3);
            pa[2 * nf]     = *(uint32_t*)&h01;
            pa[2 * nf + 1] = *(uint32_t*)&h23;
        }
        l0 = l0 * a0 + s0;
        l1 = l1 * a1 + s1;
#pragma unroll
        for (int nf = 0; nf < 8; nf++) {
            oacc[nf][0] *= a0; oacc[nf][1] *= a0;
            oacc[nf][2] *= a1; oacc[nf][3] *= a1;
        }

        // ---- O += P @ V   (V via ldmatrix.x4.trans: two d-fragments per op)
#pragma unroll
        for (int kf2 = 0; kf2 < 4; kf2++) {
            uint32_t a[4] = { pa[4 * kf2], pa[4 * kf2 + 1], pa[4 * kf2 + 2], pa[4 * kf2 + 3] };
#pragma unroll
            for (int nfp = 0; nfp < 4; nfp++) {
                uint32_t bv[4];
                int vrow = kf2 * 16 + (lane & 15);
                int c8 = nfp * 2 + (lane >> 4);     // lanes 0-15: nf=2*nfp, 16-31: nf=2*nfp+1
                ldsm_x4t(vb + vrow * 128 + ((c8 ^ (vrow & 7)) << 4), bv);
                mma_f16(oacc[2 * nfp],     a, &bv[0]);
                mma_f16(oacc[2 * nfp + 1], a, &bv[2]);
            }
        }
        __syncthreads();
    }

    l0 += __shfl_xor_sync(0xffffffff, l0, 1);
    l0 += __shfl_xor_sync(0xffffffff, l0, 2);
    l1 += __shfl_xor_sync(0xffffffff, l1, 1);
    l1 += __shfl_xor_sync(0xffffffff, l1, 2);
    float inv0 = 1.f / l0, inv1 = 1.f / l1;

    int r0 = lane >> 2;
    size_t row0 = (size_t)(b * T_SEQ + q0 + w * 16 + r0) * EMB;
    size_t row1 = row0 + 8 * EMB;
#pragma unroll
    for (int nf = 0; nf < 8; nf++) {
        int col = h * 64 + nf * 8 + (lane & 3) * 2;
        __half2 o01 = __floats2half2_rn(oacc[nf][0] * inv0, oacc[nf][1] * inv0);
        __half2 o23 = __floats2half2_rn(oacc[nf][2] * inv1, oacc[nf][3] * inv1);
        *(__half2*)(g_atth + row0 + col) = o01;
        *(__half2*)(g_atth + row1 + col) = o23;
    }
}

// ---------------- launch ----------------
extern "C" void kernel_launch(void* const* d_in, const int* in_sizes, int n_in,
                              void* d_out, int out_size) {
    const float* x      = (const float*)d_in[0];
    const float* cosb   = (const float*)d_in[1];
    const float* sinb   = (const float*)d_in[2];
    const float* attn_w = (const float*)d_in[3];
    const float* proj_w = (const float*)d_in[4];
    float* out = (float*)d_out;

    __half *xh, *w1h, *w2h, *atth;
    cudaGetSymbolAddress((void**)&xh, g_xh);
    cudaGetSymbolAddress((void**)&w1h, g_w1h);
    cudaGetSymbolAddress((void**)&w2h, g_w2h);
    cudaGetSymbolAddress((void**)&atth, g_atth);

    cudaFuncSetAttribute(gemm_hmma<0>, cudaFuncAttributeMaxDynamicSharedMemorySize, GEMM_SMEM);
    cudaFuncSetAttribute(gemm_hmma<1>, cudaFuncAttributeMaxDynamicSharedMemorySize, GEMM_SMEM);
    cudaFuncSetAttribute(attn_hmma, cudaFuncAttributeMaxDynamicSharedMemorySize, ATT_SMEM);

    // convert inputs to fp16
    {
        int n4 = BT_TOTAL * EMB / 4;
        to_half<<<(n4 + 255) / 256, 256>>>(x, xh, n4);
        n4 = FD * EMB / 4;
        to_half<<<(n4 + 255) / 256, 256>>>(attn_w, w1h, n4);
        n4 = EMB * EMB / 4;
        to_half<<<(n4 + 255) / 256, 256>>>(proj_w, w2h, n4);
    }

    // 1) qkv = x @ attn_w^T with fused rope + scatter to fp16 q/k/v
    gemm_hmma<1><<<dim3(FD / 128, BT_TOTAL / 128), 128, GEMM_SMEM>>>(
        xh, w1h, nullptr, FD, cosb, sinb);

    // 2) HMMA flash attention -> g_atth (fp16)
    attn_hmma<<<dim3(T_SEQ / ABR, 2 * NH), 256, ATT_SMEM>>>();

    // 3) out = att @ proj_w^T (fp32 out)
    gemm_hmma<0><<<dim3(EMB / 128, BT_TOTAL / 128), 128, GEMM_SMEM>>>(
        atth, w2h, out, EMB, nullptr, nullptr);
}